// round 17
// baseline (speedup 1.0000x reference)
#include <cuda_runtime.h>
#include <cuda_bf16.h>

#define NB   2
#define SEQ  2048
#define DM   512
#define NH   8
#define HD   64
#define GHD  (NB*NH)      /* 16 global heads */
#define EPSV 1e-8f

// ---------------- tensor-core helpers ----------------
__device__ __forceinline__ void ldsm4(unsigned& r0, unsigned& r1, unsigned& r2, unsigned& r3, unsigned addr) {
    asm volatile("ldmatrix.sync.aligned.m8n8.x4.shared.b16 {%0,%1,%2,%3}, [%4];"
        : "=r"(r0), "=r"(r1), "=r"(r2), "=r"(r3) : "r"(addr));
}
__device__ __forceinline__ void ldsm4t(unsigned& r0, unsigned& r1, unsigned& r2, unsigned& r3, unsigned addr) {
    asm volatile("ldmatrix.sync.aligned.m8n8.x4.trans.shared.b16 {%0,%1,%2,%3}, [%4];"
        : "=r"(r0), "=r"(r1), "=r"(r2), "=r"(r3) : "r"(addr));
}
__device__ __forceinline__ void mma16816(float* c, unsigned a0, unsigned a1, unsigned a2, unsigned a3,
                                         unsigned b0, unsigned b1) {
    asm volatile("mma.sync.aligned.m16n8k16.row.col.f32.bf16.bf16.f32 "
        "{%0,%1,%2,%3}, {%4,%5,%6,%7}, {%8,%9}, {%0,%1,%2,%3};"
        : "+f"(c[0]), "+f"(c[1]), "+f"(c[2]), "+f"(c[3])
        : "r"(a0), "r"(a1), "r"(a2), "r"(a3), "r"(b0), "r"(b1));
}
__device__ __forceinline__ void bf16split(float x, __nv_bfloat16& h, __nv_bfloat16& l) {
    h = __float2bfloat16(x);
    l = __float2bfloat16(x - __bfloat162float(h));
}
__device__ __forceinline__ void cp16(unsigned dst, const void* src) {
    asm volatile("cp.async.cg.shared.global [%0], [%1], 16;" :: "r"(dst), "l"(src));
}
#define CP_COMMIT() asm volatile("cp.async.commit_group;" ::: "memory")
#define CP_WAIT1()  asm volatile("cp.async.wait_group 1;"  ::: "memory")
#define CP_WAIT0()  asm volatile("cp.async.wait_group 0;"  ::: "memory")

// ---------------- scratch (static device globals; all bf16 hi/lo pairs) ----------------
__device__ __nv_bfloat16 g_XH[NB*SEQ*DM], g_XL[NB*SEQ*DM];   // sequence
__device__ __nv_bfloat16 g_WH[4*DM*DM],  g_WL[4*DM*DM];      // Wq,Wk,Wv,Wo
__device__ __nv_bfloat16 g_QH[GHD*SEQ*HD], g_QL[GHD*SEQ*HD];
__device__ __nv_bfloat16 g_KH[GHD*SEQ*HD], g_KL[GHD*SEQ*HD];
__device__ __nv_bfloat16 g_VH[GHD*SEQ*HD], g_VL[GHD*SEQ*HD];
__device__ __nv_bfloat16 g_AH[NB*SEQ*DM],  g_AL[NB*SEQ*DM];  // attended

// ================= xPos rotary helper =================
__device__ __forceinline__ void rope_pair(float& x1, float& x2, int deven, float pf, bool down)
{
    float sv   = ((float)deven + 25.6f) * (1.0f / 89.6f);
    float invf = powf(10000.0f, -(float)deven * (1.0f / 64.0f));
    float th   = pf * invf;
    float sn, cs;
    sincosf(th, &sn, &cs);
    float sc = powf(sv, pf * (1.0f / 512.0f));
    if (down) sc = 1.0f / sc;
    float y1 = (x1 * cs - x2 * sn) * sc;
    float y2 = (x2 * cs + x1 * sn) * sc;
    x1 = y1; x2 = y2;
}

// ================= Kernel 0: one-shot fp32 -> bf16 hi/lo conversion =================
#define X_F4 ((NB*SEQ*DM)/4)     /* 524288 */
#define W_F4 ((DM*DM)/4)         /* 65536 = 2^16 */

__global__ __launch_bounds__(256) void convert_kernel(
    const float* __restrict__ X,
    const float* __restrict__ Wq, const float* __restrict__ Wk,
    const float* __restrict__ Wv, const float* __restrict__ Wo)
{
    int gid = blockIdx.x * 256 + threadIdx.x;          // float4 index
    const float* src; __nv_bfloat16 *dh, *dl; int off;
    if (gid < X_F4) {
        src = X; dh = g_XH; dl = g_XL; off = gid;
    } else {
        int t = gid - X_F4;
        int w = t >> 16;                // 65536 float4 per weight
        off   = t & (W_F4 - 1);
        src = (w == 0) ? Wq : (w == 1) ? Wk : (w == 2) ? Wv : Wo;
        dh = g_WH + w * DM * DM; dl = g_WL + w * DM * DM;
    }
    float4 v = ((const float4*)src)[off];
    __nv_bfloat16 h0,h1,h2,h3,l0,l1,l2,l3;
    bf16split(v.x,h0,l0); bf16split(v.y,h1,l1); bf16split(v.z,h2,l2); bf16split(v.w,h3,l3);
    __nv_bfloat162* ph = (__nv_bfloat162*)(dh + off * 4);
    __nv_bfloat162* pl = (__nv_bfloat162*)(dl + off * 4);
    ph[0] = __halves2bfloat162(h0,h1); ph[1] = __halves2bfloat162(h2,h3);
    pl[0] = __halves2bfloat162(l0,l1); pl[1] = __halves2bfloat162(l2,l3);
}

// B-pair ldsm4 lane offset (bytes): n-tile pair, K-major smem stride 144 B
#define BOFF4(lane) ((unsigned)((((lane) & 7) + (((lane) >> 4) * 8)) * 144 + ((((lane) >> 3) & 1) * 16)))

// GEMM stage layout (bytes): XH 0 | XL 9216 | WH 18432 | WL 27648, stage size 36864
#define GSTG 36864
#define GEMM_SMEM (2*GSTG)

// ================= Kernel 1: QKV projection, cp.async double-buffered k-loop =================
__global__ __launch_bounds__(256) void qkv_mma(
    const float* __restrict__ bq, const float* __restrict__ bk, const float* __restrict__ bv,
    const int* __restrict__ positions)
{
    extern __shared__ char dsm[];
    const unsigned sb = (unsigned)__cvta_generic_to_shared(dsm);

    const int tid  = threadIdx.x;
    const int warp = tid >> 5;
    const int lane = tid & 31;
    const int wr   = (warp >> 1) * 16;
    const int wc   = (warp & 1) * 32;
    const int r0   = blockIdx.x * 64;
    const int c0   = blockIdx.y * 64;
    const int kind = c0 / DM;
    const int cW   = c0 % DM;
    const int h    = cW >> 6;

    const __nv_bfloat16* WHg = g_WH + (size_t)kind * DM * DM;
    const __nv_bfloat16* WLg = g_WL + (size_t)kind * DM * DM;

    float o[4][4];
    #pragma unroll
    for (int n = 0; n < 4; ++n)
        #pragma unroll
        for (int r = 0; r < 4; ++r) o[n][r] = 0.0f;

    const unsigned aoffA = (unsigned)((lane & 15) * 72 + (lane >> 4) * 8);
    const unsigned boff4 = BOFF4(lane);

    // prefetch kb=0 into stage 0
    #pragma unroll
    for (int q = 0; q < 2; ++q) {
        int it = tid + q * 256;
        int rr = it >> 3, f8 = (it & 7) * 8;
        unsigned d = (unsigned)((rr * 72 + f8) * 2);
        cp16(sb + d,         &g_XH[(size_t)(r0+rr)*DM + f8]);
        cp16(sb + d + 9216,  &g_XL[(size_t)(r0+rr)*DM + f8]);
        cp16(sb + d + 18432, &WHg[(size_t)(cW+rr)*DM + f8]);
        cp16(sb + d + 27648, &WLg[(size_t)(cW+rr)*DM + f8]);
    }
    CP_COMMIT();

    for (int kbi = 0; kbi < 8; ++kbi) {
        if (kbi + 1 < 8) {
            const int kb2 = (kbi + 1) * 64;
            const unsigned st2 = (unsigned)(((kbi + 1) & 1) * GSTG);
            #pragma unroll
            for (int q = 0; q < 2; ++q) {
                int it = tid + q * 256;
                int rr = it >> 3, f8 = (it & 7) * 8;
                unsigned d = st2 + (unsigned)((rr * 72 + f8) * 2);
                cp16(sb + d,         &g_XH[(size_t)(r0+rr)*DM + kb2 + f8]);
                cp16(sb + d + 9216,  &g_XL[(size_t)(r0+rr)*DM + kb2 + f8]);
                cp16(sb + d + 18432, &WHg[(size_t)(cW+rr)*DM + kb2 + f8]);
                cp16(sb + d + 27648, &WLg[(size_t)(cW+rr)*DM + kb2 + f8]);
            }
            CP_COMMIT();
            CP_WAIT1();
        } else {
            CP_WAIT0();
        }
        __syncthreads();

        const unsigned st = sb + (unsigned)((kbi & 1) * GSTG);
        #pragma unroll
        for (int kt = 0; kt < 4; ++kt) {
            unsigned aH0,aH1,aH2,aH3, aL0,aL1,aL2,aL3;
            unsigned abase = (aoffA + (unsigned)(kt * 16)) * 2u + (unsigned)(wr * 144);
            ldsm4(aH0,aH1,aH2,aH3, st + abase);
            ldsm4(aL0,aL1,aL2,aL3, st + 9216u + abase);
            #pragma unroll
            for (int np = 0; np < 4; np += 2) {
                unsigned bH0,bH1,bH2,bH3, bL0,bL1,bL2,bL3;
                unsigned bbase = boff4 + (unsigned)((wc + np * 8) * 144) + (unsigned)(kt * 32);
                ldsm4(bH0,bH1,bH2,bH3, st + 18432u + bbase);
                ldsm4(bL0,bL1,bL2,bL3, st + 27648u + bbase);
                mma16816(o[np],   aH0,aH1,aH2,aH3, bH0,bH1);
                mma16816(o[np],   aL0,aL1,aL2,aL3, bH0,bH1);
                mma16816(o[np],   aH0,aH1,aH2,aH3, bL0,bL1);
                mma16816(o[np+1], aH0,aH1,aH2,aH3, bH2,bH3);
                mma16816(o[np+1], aL0,aL1,aL2,aL3, bH2,bH3);
                mma16816(o[np+1], aH0,aH1,aH2,aH3, bL2,bL3);
            }
        }
        __syncthreads();
    }

    const int lrow = wr + (lane >> 2);
    const int rA = r0 + lrow, rB = rA + 8;
    const int nA = rA >> 11, sA = rA & 2047;
    const int nBt = rB >> 11, sB = rB & 2047;
    const float* bias = (kind == 0) ? bq : (kind == 1) ? bk : bv;
    __nv_bfloat16* OH = (kind == 0) ? g_QH : (kind == 1) ? g_KH : g_VH;
    __nv_bfloat16* OL = (kind == 0) ? g_QL : (kind == 1) ? g_KL : g_VL;
    const size_t baseA = ((size_t)(nA  * NH + h) * SEQ + sA) * HD;
    const size_t baseB = ((size_t)(nBt * NH + h) * SEQ + sB) * HD;
    float pfA = 0.f, pfB = 0.f;
    if (kind != 2) { pfA = (float)positions[rA]; pfB = (float)positions[rB]; }

    #pragma unroll
    for (int n = 0; n < 4; ++n) {
        int d0 = wc + n * 8 + (lane & 3) * 2;
        float b0 = bias[cW + d0], b1 = bias[cW + d0 + 1];
        float vA0 = o[n][0] + b0, vA1 = o[n][1] + b1;
        float vB0 = o[n][2] + b0, vB1 = o[n][3] + b1;
        if (kind != 2) {
            if (kind == 0) { vA0 *= 0.125f; vA1 *= 0.125f; vB0 *= 0.125f; vB1 *= 0.125f; }
            bool down = (kind == 1);
            rope_pair(vA0, vA1, d0, pfA, down);
            rope_pair(vB0, vB1, d0, pfB, down);
        }
        __nv_bfloat16 h0,h1,l0,l1;
        bf16split(vA0,h0,l0); bf16split(vA1,h1,l1);
        *(__nv_bfloat162*)&OH[baseA + d0] = __halves2bfloat162(h0,h1);
        *(__nv_bfloat162*)&OL[baseA + d0] = __halves2bfloat162(l0,l1);
        bf16split(vB0,h0,l0); bf16split(vB1,h1,l1);
        *(__nv_bfloat162*)&OH[baseB + d0] = __halves2bfloat162(h0,h1);
        *(__nv_bfloat162*)&OL[baseB + d0] = __halves2bfloat162(l0,l1);
    }
}

// ================= Kernel 2: tensor-core attention (R16 + parallel 4-thread/row scan) =================
#define SO_QH   0
#define SO_QL   9216
#define SO_K0   18432            /* KH buf0; KL at +9216 */
#define SO_K1   36864            /* KH buf1; KL at +9216 */
#define SO_VH   55296            /* V row-major [t][d], stride 72 */
#define SO_VL   64512
#define SO_WHo  73728            /* weights bf16 hi, [row][col] stride 72 */
#define SO_WLo  82944
#define SO_AS   92160            /* fp32 sigmoid A, [row][col] stride 68 */
#define SO_WB   109568           /* fp32 [64] boundary weights */
#define SO_MS   109824           /* fp32 [64] mask tile */
#define ATTN_SMEM 110080

__global__ __launch_bounds__(256, 2) void attn_kernel(const float* __restrict__ mask)
{
    extern __shared__ char smc[];
    __nv_bfloat16* QH  = (__nv_bfloat16*)(smc + SO_QH);
    __nv_bfloat16* QL  = (__nv_bfloat16*)(smc + SO_QL);
    __nv_bfloat16* WHs = (__nv_bfloat16*)(smc + SO_WHo);
    __nv_bfloat16* WLs = (__nv_bfloat16*)(smc + SO_WLo);
    float* AS  = (float*)(smc + SO_AS);
    float* WB  = (float*)(smc + SO_WB);
    float* MS  = (float*)(smc + SO_MS);

    const unsigned sb = (unsigned)__cvta_generic_to_shared(smc);

    const int tid  = threadIdx.x;
    const int warp = tid >> 5;
    const int lane = tid & 31;
    const int wr   = (warp >> 1) * 16;
    const int wc   = (warp & 1) * 32;
    const int sr   = tid >> 2;               // scan row 0..63
    const int sq   = tid & 3;                // scan segment 0..3
    const int gh   = blockIdx.y;
    const int nb   = gh >> 3;
    const int hh   = gh & 7;
    const int rb   = (int)(gridDim.x - 1 - blockIdx.x);   // heavy blocks first
    const int s0   = rb * 64;

    const __nv_bfloat16* QHg = g_QH + (size_t)gh * SEQ * HD;
    const __nv_bfloat16* QLg = g_QL + (size_t)gh * SEQ * HD;
    const __nv_bfloat16* KHg = g_KH + (size_t)gh * SEQ * HD;
    const __nv_bfloat16* KLg = g_KL + (size_t)gh * SEQ * HD;
    const __nv_bfloat16* VHg = g_VH + (size_t)gh * SEQ * HD;
    const __nv_bfloat16* VLg = g_VL + (size_t)gh * SEQ * HD;

    // ---- copy Q tile (sync, once) ----
    for (int it = tid; it < 512; it += 256) {
        int rr = it >> 3, f8 = (it & 7) * 8;
        *(uint4*)&QH[rr*72 + f8] = *(const uint4*)&QHg[(size_t)(s0+rr)*HD + f8];
        *(uint4*)&QL[rr*72 + f8] = *(const uint4*)&QLg[(size_t)(s0+rr)*HD + f8];
    }

    // ---- prefetch K(rb) into buf0 ----
    {
        const int lo0 = rb * 64;
        #pragma unroll
        for (int q = 0; q < 2; ++q) {
            int it = tid + q * 256;
            int rr = it >> 3, f8 = (it & 7) * 8;
            unsigned d = (unsigned)SO_K0 + (unsigned)((rr * 72 + f8) * 2);
            cp16(sb + d,        &KHg[(size_t)(lo0 + rr) * HD + f8]);
            cp16(sb + d + 9216, &KLg[(size_t)(lo0 + rr) * HD + f8]);
        }
    }
    CP_COMMIT();

    float cA = 0.0f;
    float cP = 1.0f;

    float o[4][4];
    #pragma unroll
    for (int n = 0; n < 4; ++n)
        #pragma unroll
        for (int r = 0; r < 4; ++r) o[n][r] = 0.0f;

    const unsigned aoffA = (unsigned)((lane & 15) * 72 + (lane >> 4) * 8);
    const unsigned boff4 = BOFF4(lane);
    const unsigned toff4 = (unsigned)((lane & 15) * 144 + (lane >> 4) * 16);   // trans-V n-pair

    for (int jb = rb; jb >= 0; --jb) {
        const int lo = jb * 64;
        const unsigned curK = ((rb - jb) & 1) ? (unsigned)SO_K1 : (unsigned)SO_K0;
        const unsigned nxtK = ((rb - jb) & 1) ? (unsigned)SO_K0 : (unsigned)SO_K1;

        // group A: V(jb) row-major + mask tile
        #pragma unroll
        for (int q = 0; q < 2; ++q) {
            int it = tid + q * 256;
            int rr = it >> 3, f8 = (it & 7) * 8;
            unsigned d = (unsigned)((rr * 72 + f8) * 2);
            cp16(sb + SO_VH + d, &VHg[(size_t)(lo + rr) * HD + f8]);
            cp16(sb + SO_VL + d, &VLg[(size_t)(lo + rr) * HD + f8]);
        }
        if (tid < 16) cp16(sb + SO_MS + (unsigned)(tid * 16), &mask[(size_t)nb * SEQ + lo + tid * 4]);
        CP_COMMIT();
        // group B: K(jb-1) into alternate buffer
        if (jb > 0) {
            #pragma unroll
            for (int q = 0; q < 2; ++q) {
                int it = tid + q * 256;
                int rr = it >> 3, f8 = (it & 7) * 8;
                unsigned d = nxtK + (unsigned)((rr * 72 + f8) * 2);
                cp16(sb + d,        &KHg[(size_t)(lo - 64 + rr) * HD + f8]);
                cp16(sb + d + 9216, &KLg[(size_t)(lo - 64 + rr) * HD + f8]);
            }
        }
        CP_COMMIT();
        CP_WAIT1();
        __syncthreads();            // (a)

        // ---- S = Q K^T via 3-pass bf16 split MMA (paired B ldsm4) ----
        float sc[4][4];
        #pragma unroll
        for (int n = 0; n < 4; ++n)
            #pragma unroll
            for (int r = 0; r < 4; ++r) sc[n][r] = 0.0f;

        #pragma unroll
        for (int kt = 0; kt < 4; ++kt) {
            unsigned aH0,aH1,aH2,aH3, aL0,aL1,aL2,aL3;
            unsigned abase = (aoffA + (unsigned)(kt * 16)) * 2u;
            ldsm4(aH0,aH1,aH2,aH3, sb + SO_QH + (unsigned)(wr * 144) + abase);
            ldsm4(aL0,aL1,aL2,aL3, sb + SO_QL + (unsigned)(wr * 144) + abase);
            #pragma unroll
            for (int np = 0; np < 4; np += 2) {
                unsigned bH0,bH1,bH2,bH3, bL0,bL1,bL2,bL3;
                unsigned bbase = boff4 + (unsigned)((wc + np * 8) * 144) + (unsigned)(kt * 32);
                ldsm4(bH0,bH1,bH2,bH3, sb + curK + bbase);
                ldsm4(bL0,bL1,bL2,bL3, sb + curK + 9216u + bbase);
                mma16816(sc[np],   aH0,aH1,aH2,aH3, bH0,bH1);
                mma16816(sc[np],   aL0,aL1,aL2,aL3, bH0,bH1);
                mma16816(sc[np],   aH0,aH1,aH2,aH3, bL0,bL1);
                mma16816(sc[np+1], aH0,aH1,aH2,aH3, bH2,bH3);
                mma16816(sc[np+1], aL0,aL1,aL2,aL3, bH2,bH3);
                mma16816(sc[np+1], aH0,aH1,aH2,aH3, bL2,bL3);
            }
        }

        // ---- sigmoid * mask * causal on fragments -> AS[row][col] ----
        {
            const int lrow = wr + (lane >> 2);
            #pragma unroll
            for (int n = 0; n < 4; ++n) {
                const int lc = wc + n * 8 + (lane & 3) * 2;
                float m0 = MS[lc], m1 = MS[lc + 1];
                float a0 = 0.f, a1 = 0.f, a2 = 0.f, a3 = 0.f;
                if (lo + lc     <= s0 + lrow)     a0 = __fdividef(m0, 1.0f + __expf(-sc[n][0]));
                if (lo + lc + 1 <= s0 + lrow)     a1 = __fdividef(m1, 1.0f + __expf(-sc[n][1]));
                if (lo + lc     <= s0 + lrow + 8) a2 = __fdividef(m0, 1.0f + __expf(-sc[n][2]));
                if (lo + lc + 1 <= s0 + lrow + 8) a3 = __fdividef(m1, 1.0f + __expf(-sc[n][3]));
                *(float2*)&AS[lrow * 68 + lc]       = make_float2(a0, a1);
                *(float2*)&AS[(lrow + 8) * 68 + lc] = make_float2(a2, a3);
            }
        }
        __syncthreads();            // (b)

        // ---- parallel suffix-product scan: 4 threads/row, 16 cols each (R8-proven mapping) ----
        {
            float a[16];
            float4 f0 = *(const float4*)&AS[sr * 68 + sq * 16 + 0];
            float4 f1 = *(const float4*)&AS[sr * 68 + sq * 16 + 4];
            float4 f2 = *(const float4*)&AS[sr * 68 + sq * 16 + 8];
            float4 f3 = *(const float4*)&AS[sr * 68 + sq * 16 + 12];
            a[0]=f0.x; a[1]=f0.y; a[2]=f0.z; a[3]=f0.w;
            a[4]=f1.x; a[5]=f1.y; a[6]=f1.z; a[7]=f1.w;
            a[8]=f2.x; a[9]=f2.y; a[10]=f2.z; a[11]=f2.w;
            a[12]=f3.x; a[13]=f3.y; a[14]=f3.z; a[15]=f3.w;

            float pp = 1.0f;
            #pragma unroll
            for (int i = 15; i >= 0; --i) pp *= (1.0f - a[i]) + EPSV;

            float p0 = __shfl_sync(0xffffffffu, pp, 0, 4);
            float p1 = __shfl_sync(0xffffffffu, pp, 1, 4);
            float p2 = __shfl_sync(0xffffffffu, pp, 2, 4);
            float p3 = __shfl_sync(0xffffffffu, pp, 3, 4);
            float aN = __shfl_down_sync(0xffffffffu, a[0], 1, 4);  // a[0] of next segment

            float lA = (sq == 3) ? cA : aN;
            float lP = cP;
            if (sq < 3) lP *= p3;
            if (sq < 2) lP *= p2;
            if (sq < 1) lP *= p1;

            #pragma unroll
            for (int i = 15; i >= 0; --i) {
                float Pn = ((1.0f - a[i]) + EPSV) * lP;
                float w  = lA * Pn;
                int t = sq * 16 + i + 1;
                if (t == 64) WB[sr] = w;
                else { __nv_bfloat16 h, l; bf16split(w, h, l); WHs[sr*72 + t] = h; WLs[sr*72 + t] = l; }
                lA = a[i]; lP = Pn;
            }
            if (sq == 0) {
                float w0 = (jb == 0) ? lA : 0.0f;
                __nv_bfloat16 h, l; bf16split(w0, h, l);
                WHs[sr * 72] = h; WLs[sr * 72] = l;
            }
            cP = cP * p3 * p2 * p1 * p0;
            cA = __shfl_sync(0xffffffffu, a[0], 0, 4);
        }
        __syncthreads();            // (c)

        // ---- out += W * V via 3-pass bf16 split MMA (paired trans ldsm4) ----
        #pragma unroll
        for (int kt = 0; kt < 4; ++kt) {
            unsigned aH0,aH1,aH2,aH3, aL0,aL1,aL2,aL3;
            unsigned abase = (aoffA + (unsigned)(kt * 16)) * 2u;
            ldsm4(aH0,aH1,aH2,aH3, sb + SO_WHo + (unsigned)(wr * 144) + abase);
            ldsm4(aL0,aL1,aL2,aL3, sb + SO_WLo + (unsigned)(wr * 144) + abase);
            unsigned tb = (unsigned)(kt * 16 * 144) + toff4;
            #pragma unroll
            for (int np = 0; np < 4; np += 2) {
                unsigned bH0,bH1,bH2,bH3, bL0,bL1,bL2,bL3;
                unsigned bbase = tb + (unsigned)((wc + np * 8) * 2);
                ldsm4t(bH0,bH1,bH2,bH3, sb + SO_VH + bbase);
                ldsm4t(bL0,bL1,bL2,bL3, sb + SO_VL + bbase);
                mma16816(o[np],   aH0,aH1,aH2,aH3, bH0,bH1);
                mma16816(o[np],   aL0,aL1,aL2,aL3, bH0,bH1);
                mma16816(o[np],   aH0,aH1,aH2,aH3, bL0,bL1);
                mma16816(o[np+1], aH0,aH1,aH2,aH3, bH2,bH3);
                mma16816(o[np+1], aL0,aL1,aL2,aL3, bH2,bH3);
                mma16816(o[np+1], aH0,aH1,aH2,aH3, bL2,bL3);
            }
        }
        // boundary column: WB x V row lo+64
        if (jb < rb) {
            size_t vb = (size_t)(lo + 64) * HD;
            float wb0 = WB[wr + (lane >> 2)];
            float wb1 = WB[wr + (lane >> 2) + 8];
            #pragma unroll
            for (int n = 0; n < 4; ++n) {
                int d0 = wc + n * 8 + (lane & 3) * 2;
                __nv_bfloat162 hp = *(const __nv_bfloat162*)&VHg[vb + d0];
                __nv_bfloat162 lp = *(const __nv_bfloat162*)&VLg[vb + d0];
                float v0 = __bfloat162float(hp.x) + __bfloat162float(lp.x);
                float v1 = __bfloat162float(hp.y) + __bfloat162float(lp.y);
                o[n][0] = fmaf(wb0, v0, o[n][0]);
                o[n][1] = fmaf(wb0, v1, o[n][1]);
                o[n][2] = fmaf(wb1, v0, o[n][2]);
                o[n][3] = fmaf(wb1, v1, o[n][3]);
            }
        }
        __syncthreads();            // (d)
    }

    // ---- write attended fragments as bf16 hi/lo ----
    {
        const int lrow = wr + (lane >> 2);
        #pragma unroll
        for (int n = 0; n < 4; ++n) {
            const int d0 = wc + n * 8 + (lane & 3) * 2;
            size_t bA = ((size_t)(nb * SEQ + s0 + lrow)) * DM + hh * HD + d0;
            size_t bB = ((size_t)(nb * SEQ + s0 + lrow + 8)) * DM + hh * HD + d0;
            __nv_bfloat16 h0,h1,l0,l1;
            bf16split(o[n][0],h0,l0); bf16split(o[n][1],h1,l1);
            *(__nv_bfloat162*)&g_AH[bA] = __halves2bfloat162(h0,h1);
            *(__nv_bfloat162*)&g_AL[bA] = __halves2bfloat162(l0,l1);
            bf16split(o[n][2],h0,l0); bf16split(o[n][3],h1,l1);
            *(__nv_bfloat162*)&g_AH[bB] = __halves2bfloat162(h0,h1);
            *(__nv_bfloat162*)&g_AL[bB] = __halves2bfloat162(l0,l1);
        }
    }
}

// ================= Kernel 3: output projection, cp.async double-buffered k-loop =================
__global__ __launch_bounds__(256) void oproj_mma(
    const float* __restrict__ bo, float* __restrict__ outp)
{
    extern __shared__ char dsm[];
    const unsigned sb = (unsigned)__cvta_generic_to_shared(dsm);

    const int tid  = threadIdx.x;
    const int warp = tid >> 5;
    const int lane = tid & 31;
    const int wr   = (warp >> 1) * 16;
    const int wc   = (warp & 1) * 32;
    const int r0   = blockIdx.x * 64;
    const int c0   = blockIdx.y * 64;

    const __nv_bfloat16* WHg = g_WH + (size_t)3 * DM * DM;
    const __nv_bfloat16* WLg = g_WL + (size_t)3 * DM * DM;

    float o[4][4];
    #pragma unroll
    for (int n = 0; n < 4; ++n)
        #pragma unroll
        for (int r = 0; r < 4; ++r) o[n][r] = 0.0f;

    const unsigned aoffA = (unsigned)((lane & 15) * 72 + (lane >> 4) * 8);
    const unsigned boff4 = BOFF4(lane);

    #pragma unroll
    for (int q = 0; q < 2; ++q) {
        int it = tid + q * 256;
        int rr = it >> 3, f8 = (it & 7) * 8;
        unsigned d = (unsigned)((rr * 72 + f8) * 2);
        cp16(sb + d,         &g_AH[(size_t)(r0+rr)*DM + f8]);
        cp16(sb + d + 9216,  &g_AL[(size_t)(r0+rr)*DM + f8]);
        cp16(sb + d + 18432, &WHg[(size_t)(c0+rr)*DM + f8]);
        cp16(sb + d + 27648, &WLg[(size_t)(c0+rr)*DM + f8]);
    }
    CP_COMMIT();

    for (int kbi = 0; kbi < 8; ++kbi) {
        if (kbi + 1 < 8) {
            const int kb2 = (kbi + 1) * 64;
            const unsigned st2 = (unsigned)(((kbi + 1) & 1) * GSTG);
            #pragma unroll
            for (int q = 0; q < 2; ++q) {
                int it = tid + q * 256;
                int rr = it >> 3, f8 = (it & 7) * 8;
                unsigned d = st2 + (unsigned)((rr * 72 + f8) * 2);
                cp16(sb + d,         &g_AH[(size_t)(r0+rr)*DM + kb2 + f8]);
                cp16(sb + d + 9216,  &g_AL[(size_t)(r0+rr)*DM + kb2 + f8]);
                cp16(sb + d + 18432, &WHg[(size_t)(c0+rr)*DM + kb2 + f8]);
                cp16(sb + d + 27648, &WLg[(size_t)(c0+rr)*DM + kb2 + f8]);
            }
            CP_COMMIT();
            CP_WAIT1();
        } else {
            CP_WAIT0();
        }
        __syncthreads();

        const unsigned st = sb + (unsigned)((kbi & 1) * GSTG);
        #pragma unroll
        for (int kt = 0; kt < 4; ++kt) {
            unsigned aH0,aH1,aH2,aH3, aL0,aL1,aL2,aL3;
            unsigned abase = (aoffA + (unsigned)(kt * 16)) * 2u + (unsigned)(wr * 144);
            ldsm4(aH0,aH1,aH2,aH3, st + abase);
            ldsm4(aL0,aL1,aL2,aL3, st + 9216u + abase);
            #pragma unroll
            for (int np = 0; np < 4; np += 2) {
                unsigned bH0,bH1,bH2,bH3, bL0,bL1,bL2,bL3;
                unsigned bbase = boff4 + (unsigned)((wc + np * 8) * 144) + (unsigned)(kt * 32);
                ldsm4(bH0,bH1,bH2,bH3, st + 18432u + bbase);
                ldsm4(bL0,bL1,bL2,bL3, st + 27648u + bbase);
                mma16816(o[np],   aH0,aH1,aH2,aH3, bH0,bH1);
                mma16816(o[np],   aL0,aL1,aL2,aL3, bH0,bH1);
                mma16816(o[np],   aH0,aH1,aH2,aH3, bL0,bL1);
                mma16816(o[np+1], aH0,aH1,aH2,aH3, bH2,bH3);
                mma16816(o[np+1], aL0,aL1,aL2,aL3, bH2,bH3);
                mma16816(o[np+1], aH0,aH1,aH2,aH3, bL2,bL3);
            }
        }
        __syncthreads();
    }

    const int lrow = wr + (lane >> 2);
    const int rA = r0 + lrow, rB = rA + 8;
    #pragma unroll
    for (int n = 0; n < 4; ++n) {
        int d0 = wc + n * 8 + (lane & 3) * 2;
        float b0 = bo[c0 + d0], b1 = bo[c0 + d0 + 1];
        *(float2*)&outp[(size_t)rA * DM + c0 + d0] = make_float2(o[n][0] + b0, o[n][1] + b1);
        *(float2*)&outp[(size_t)rB * DM + c0 + d0] = make_float2(o[n][2] + b0, o[n][3] + b1);
    }
}

// ================= host launcher =================
extern "C" void kernel_launch(void* const* d_in, const int* in_sizes, int n_in,
                              void* d_out, int out_size)
{
    const float* seqp = nullptr;
    const float* maskp = nullptr;
    const int*   posp = nullptr;
    const float* W[4] = {nullptr, nullptr, nullptr, nullptr};
    const float* B[4] = {nullptr, nullptr, nullptr, nullptr};
    int nw = 0, nbb = 0, n4096 = 0;
    for (int i = 0; i < n_in; ++i) {
        int sz = in_sizes[i];
        if (sz == NB * SEQ * DM) {
            seqp = (const float*)d_in[i];
        } else if (sz == DM * DM) {
            if (nw < 4) W[nw++] = (const float*)d_in[i];
        } else if (sz == DM) {
            if (nbb < 4) B[nbb++] = (const float*)d_in[i];
        } else if (sz == NB * SEQ) {
            if (n4096 == 0) maskp = (const float*)d_in[i];
            else            posp  = (const int*)d_in[i];
            ++n4096;
        }
    }

    cudaFuncSetAttribute(attn_kernel, cudaFuncAttributeMaxDynamicSharedMemorySize, ATTN_SMEM);
    cudaFuncSetAttribute(qkv_mma,   cudaFuncAttributeMaxDynamicSharedMemorySize, GEMM_SMEM);
    cudaFuncSetAttribute(oproj_mma, cudaFuncAttributeMaxDynamicSharedMemorySize, GEMM_SMEM);

    convert_kernel<<<(X_F4 + 4 * W_F4) / 256, 256>>>(seqp, W[0], W[1], W[2], W[3]);
    qkv_mma<<<dim3(64, 24), 256, GEMM_SMEM>>>(B[0], B[1], B[2], posp);
    attn_kernel<<<dim3(32, 16), 256, ATTN_SMEM>>>(maskp);
    oproj_mma<<<dim3(64, 8), 256, GEMM_SMEM>>>(B[3], (float*)d_out);
}